// round 4
// baseline (speedup 1.0000x reference)
#include <cuda_runtime.h>
#include <cuda_bf16.h>
#include <float.h>

// LabelLoss: B=16, K=11, H=W=128, C=7
//   pooled = 3x3 box-sum (pad 1) of heatmap[b,k]  (÷9 dropped: argmax-invariant)
//   idx    = argmax over flattened HxW (first occurrence)
//   loss[b,k] = sum_c (pred[b, k*7+c, idx/W, idx%W] - gt[b,k,c])^2
//   out[b] = mean_k loss[b,k]

#define BVAL 16
#define KVAL 11
#define HVAL 128
#define WVAL 128
#define HW   (HVAL * WVAL)
#define CVAL 7
#define NTHREADS 256   // 2 threads per column, 64 rows each

__device__ float g_labelloss_scratch[BVAL * KVAL];

__global__ __launch_bounds__(NTHREADS)
void labelloss_pool_argmax_kernel(const float* __restrict__ pred,
                                  const float* __restrict__ gt,
                                  const float* __restrict__ heatmap)
{
    const int bk  = blockIdx.x;              // 0..175  (b*K + k)
    const int tid = threadIdx.x;
    const int y   = tid & (WVAL - 1);        // column 0..127
    const int x0  = (tid >> 7) * 64;         // row start: 0 or 64

    const float* __restrict__ hm = heatmap + (size_t)bk * HW;

    // rowsum(x) = hm[x][y-1] + hm[x][y] + hm[x][y+1] (missing neighbors = 0)
    auto rowsum = [&](int x) -> float {
        if (x < 0 || x >= HVAL) return 0.0f;
        const float* p = hm + x * WVAL;
        float s = p[y];
        if (y > 0)        s += p[y - 1];
        if (y < WVAL - 1) s += p[y + 1];
        return s;
    };

    float rs_m = rowsum(x0 - 1);
    float rs_c = rowsum(x0);

    float best = -FLT_MAX;
    int   bidx = 0x7FFFFFFF;

    #pragma unroll 4
    for (int x = x0; x < x0 + 64; ++x) {
        float rs_p  = rowsum(x + 1);
        float pooled = rs_m + rs_c + rs_p;
        int   idx    = x * WVAL + y;
        // strictly increasing idx within a thread -> '>' alone preserves
        // first-occurrence among this thread's candidates
        if (pooled > best) { best = pooled; bidx = idx; }
        rs_m = rs_c;
        rs_c = rs_p;
    }

    // Block reduction of (best, bidx); ties -> smaller index (first occurrence)
    __shared__ float sv[NTHREADS];
    __shared__ int   si[NTHREADS];
    sv[tid] = best;
    si[tid] = bidx;
    __syncthreads();

    #pragma unroll
    for (int s = NTHREADS / 2; s > 0; s >>= 1) {
        if (tid < s) {
            float v2 = sv[tid + s];
            int   i2 = si[tid + s];
            if (v2 > sv[tid] || (v2 == sv[tid] && i2 < si[tid])) {
                sv[tid] = v2;
                si[tid] = i2;
            }
        }
        __syncthreads();
    }

    if (tid == 0) {
        const int idx = si[0];
        const float* __restrict__ pk = pred + (size_t)bk * CVAL * HW;
        const float* __restrict__ g  = gt   + (size_t)bk * CVAL;
        float loss = 0.0f;
        #pragma unroll
        for (int c = 0; c < CVAL; ++c) {
            float d = pk[c * HW + idx] - g[c];
            loss = fmaf(d, d, loss);
        }
        g_labelloss_scratch[bk] = loss;
    }
}

__global__ void labelloss_reduce_kernel(float* __restrict__ out)
{
    const int b = threadIdx.x;
    if (b < BVAL) {
        float s = 0.0f;
        #pragma unroll
        for (int k = 0; k < KVAL; ++k)
            s += g_labelloss_scratch[b * KVAL + k];
        out[b] = s * (1.0f / (float)KVAL);
    }
}

extern "C" void kernel_launch(void* const* d_in, const int* in_sizes, int n_in,
                              void* d_out, int out_size)
{
    const float* pred    = (const float*)d_in[0];
    const float* gt      = (const float*)d_in[1];
    const float* heatmap = (const float*)d_in[2];
    float* out = (float*)d_out;

    labelloss_pool_argmax_kernel<<<BVAL * KVAL, NTHREADS>>>(pred, gt, heatmap);
    labelloss_reduce_kernel<<<1, 32>>>(out);
}

// round 5
// speedup vs baseline: 1.3692x; 1.3692x over previous
#include <cuda_runtime.h>
#include <cuda_bf16.h>
#include <float.h>

// LabelLoss: B=16, K=11, H=W=128, C=7  — single fused kernel.
//   pooled = 3x3 box-sum (pad 1) of heatmap[b,k]  (÷9 dropped: argmax-invariant)
//   idx    = argmax over flattened HxW (first occurrence)
//   loss[b,k] = sum_c (pred[b, k*7+c, idx/W, idx%W] - gt[b,k,c])^2
//   out[b] = mean_k loss[b,k]   (done by the last CTA to finish)

#define BVAL 16
#define KVAL 11
#define NBK  (BVAL * KVAL)          // 176 CTAs
#define HVAL 128
#define WVAL 128
#define HW   (HVAL * WVAL)
#define CVAL 7
#define NTHREADS 256                // 8 warps; warp w owns rows [16w, 16w+16)

__device__ float        g_labelloss_scratch[NBK];
__device__ unsigned int g_labelloss_count = 0;

__global__ __launch_bounds__(NTHREADS)
void labelloss_fused_kernel(const float* __restrict__ pred,
                            const float* __restrict__ gt,
                            const float* __restrict__ heatmap,
                            float* __restrict__ out)
{
    const int bk   = blockIdx.x;            // b*K + k
    const int tid  = threadIdx.x;
    const int lane = tid & 31;
    const int warp = tid >> 5;              // 0..7
    const int x0   = warp * 16;             // row strip start
    const int c0   = lane * 4;              // 4 columns per lane

    const float* __restrict__ hm = heatmap + (size_t)bk * HW;

    // rowsums(x): horizontal 3-tap sums for this lane's 4 columns of row x.
    // One LDG.128 per lane per row; neighbors via intra-float4 + lane shuffles.
    auto rowsums = [&](int x) -> float4 {
        float4 v;
        if ((unsigned)x < (unsigned)HVAL) {
            v = *reinterpret_cast<const float4*>(hm + x * WVAL + c0);
        } else {
            v = make_float4(0.f, 0.f, 0.f, 0.f);
        }
        float left  = __shfl_up_sync(0xffffffffu, v.w, 1);
        float right = __shfl_down_sync(0xffffffffu, v.x, 1);
        if (lane == 0)  left  = 0.f;   // column -1 pad
        if (lane == 31) right = 0.f;   // column 128 pad
        float4 r;
        r.x = left + v.x + v.y;
        r.y = v.x  + v.y + v.z;
        r.z = v.y  + v.z + v.w;
        r.w = v.z  + v.w + right;
        return r;
    };

    float4 rsm = rowsums(x0 - 1);
    float4 rsc = rowsums(x0);

    float best = -FLT_MAX;
    int   bidx = 0x7FFFFFFF;

    #pragma unroll
    for (int i = 0; i < 16; ++i) {
        const int x = x0 + i;
        float4 rsp = rowsums(x + 1);
        float p0 = rsm.x + rsc.x + rsp.x;
        float p1 = rsm.y + rsc.y + rsp.y;
        float p2 = rsm.z + rsc.z + rsp.z;
        float p3 = rsm.w + rsc.w + rsp.w;
        const int base = x * WVAL + c0;
        // ascending index + strict '>' preserves first-occurrence semantics
        if (p0 > best) { best = p0; bidx = base;     }
        if (p1 > best) { best = p1; bidx = base + 1; }
        if (p2 > best) { best = p2; bidx = base + 2; }
        if (p3 > best) { best = p3; bidx = base + 3; }
        rsm = rsc; rsc = rsp;
    }

    // Block reduction of (best, bidx); ties -> smaller index.
    __shared__ float sv[NTHREADS];
    __shared__ int   si[NTHREADS];
    sv[tid] = best;
    si[tid] = bidx;
    __syncthreads();

    #pragma unroll
    for (int s = NTHREADS / 2; s > 0; s >>= 1) {
        if (tid < s) {
            float v2 = sv[tid + s];
            int   i2 = si[tid + s];
            if (v2 > sv[tid] || (v2 == sv[tid] && i2 < si[tid])) {
                sv[tid] = v2;
                si[tid] = i2;
            }
        }
        __syncthreads();
    }

    __shared__ bool is_last;
    if (tid == 0) {
        const int idx = si[0];
        const float* __restrict__ pk = pred + (size_t)bk * CVAL * HW;
        const float* __restrict__ g  = gt   + (size_t)bk * CVAL;
        float loss = 0.0f;
        #pragma unroll
        for (int c = 0; c < CVAL; ++c) {
            float d = pk[c * HW + idx] - g[c];
            loss = fmaf(d, d, loss);
        }
        g_labelloss_scratch[bk] = loss;
        __threadfence();                                  // scratch visible before count
        unsigned v = atomicAdd(&g_labelloss_count, 1u);
        is_last = (v == NBK - 1);
    }
    __syncthreads();

    if (is_last) {
        __threadfence();                                  // acquire: see all scratch writes
        if (tid < BVAL) {
            float s = 0.0f;
            #pragma unroll
            for (int k = 0; k < KVAL; ++k)
                s += g_labelloss_scratch[tid * KVAL + k]; // fixed order -> deterministic
            out[tid] = s * (1.0f / (float)KVAL);
        }
        if (tid == 0) g_labelloss_count = 0;              // reset for next graph replay
    }
}

extern "C" void kernel_launch(void* const* d_in, const int* in_sizes, int n_in,
                              void* d_out, int out_size)
{
    const float* pred    = (const float*)d_in[0];
    const float* gt      = (const float*)d_in[1];
    const float* heatmap = (const float*)d_in[2];
    float* out = (float*)d_out;

    labelloss_fused_kernel<<<NBK, NTHREADS>>>(pred, gt, heatmap, out);
}

// round 6
// speedup vs baseline: 1.3772x; 1.0058x over previous
#include <cuda_runtime.h>
#include <cuda_bf16.h>
#include <float.h>

// LabelLoss: B=16, K=11, H=W=128, C=7 — single fused kernel, latency-optimized.
//   pooled = 3x3 box-sum (pad 1) of heatmap[b,k]  (÷9 dropped: argmax-invariant)
//   idx    = argmax over flattened HxW (first occurrence)
//   loss[b,k] = sum_c (pred[b, k*7+c, idx/W, idx%W] - gt[b,k,c])^2
//   out[b] = mean_k loss[b,k]   (last CTA to finish does the mean)

#define BVAL 16
#define KVAL 11
#define NBK  (BVAL * KVAL)          // 176 CTAs
#define HVAL 128
#define WVAL 128
#define HW   (HVAL * WVAL)
#define CVAL 7
#define NTHREADS 512                // 16 warps; warp w owns rows [8w, 8w+8)
#define NWARPS   (NTHREADS / 32)

__device__ float        g_labelloss_scratch[NBK];
__device__ unsigned int g_labelloss_count = 0;

__global__ __launch_bounds__(NTHREADS)
void labelloss_fused_kernel(const float* __restrict__ pred,
                            const float* __restrict__ gt,
                            const float* __restrict__ heatmap,
                            float* __restrict__ out)
{
    const int bk   = blockIdx.x;            // b*K + k
    const int tid  = threadIdx.x;
    const int lane = tid & 31;
    const int warp = tid >> 5;              // 0..15
    const int x0   = warp * 8;              // row strip start
    const int c0   = lane * 4;              // 4 columns per lane

    const float* __restrict__ hm = heatmap + (size_t)bk * HW;

    // ---- Phase 1: front-batch ALL loads (rows x0-1 .. x0+8) -> MLP = 10 ----
    float4 v[10];
    #pragma unroll
    for (int i = 0; i < 10; ++i) {
        const int x = x0 - 1 + i;
        if ((unsigned)x < (unsigned)HVAL) {
            v[i] = *reinterpret_cast<const float4*>(hm + x * WVAL + c0);
        } else {
            v[i] = make_float4(0.f, 0.f, 0.f, 0.f);
        }
    }

    // ---- Phase 2: horizontal 3-tap per row (shuffles + in-register adds) ----
    float4 rs[10];
    #pragma unroll
    for (int i = 0; i < 10; ++i) {
        float left  = __shfl_up_sync(0xffffffffu, v[i].w, 1);
        float right = __shfl_down_sync(0xffffffffu, v[i].x, 1);
        if (lane == 0)  left  = 0.f;   // column -1 pad
        if (lane == 31) right = 0.f;   // column 128 pad
        rs[i].x = left    + v[i].x + v[i].y;
        rs[i].y = v[i].x  + v[i].y + v[i].z;
        rs[i].z = v[i].y  + v[i].z + v[i].w;
        rs[i].w = v[i].z  + v[i].w + right;
    }

    // ---- Phase 3: vertical 3-tap + running argmax over this thread's cells ----
    float best = -FLT_MAX;
    int   bidx = 0x7FFFFFFF;
    #pragma unroll
    for (int j = 0; j < 8; ++j) {
        const int x = x0 + j;
        float p0 = rs[j].x + rs[j + 1].x + rs[j + 2].x;
        float p1 = rs[j].y + rs[j + 1].y + rs[j + 2].y;
        float p2 = rs[j].z + rs[j + 1].z + rs[j + 2].z;
        float p3 = rs[j].w + rs[j + 1].w + rs[j + 2].w;
        const int base = x * WVAL + c0;
        // ascending index + strict '>' preserves first-occurrence semantics
        if (p0 > best) { best = p0; bidx = base;     }
        if (p1 > best) { best = p1; bidx = base + 1; }
        if (p2 > best) { best = p2; bidx = base + 2; }
        if (p3 > best) { best = p3; bidx = base + 3; }
    }

    // ---- Phase 4: warp-shuffle argmax reduce (ties -> smaller index) ----
    #pragma unroll
    for (int off = 16; off > 0; off >>= 1) {
        float v2 = __shfl_down_sync(0xffffffffu, best, off);
        int   i2 = __shfl_down_sync(0xffffffffu, bidx, off);
        if (v2 > best || (v2 == best && i2 < bidx)) { best = v2; bidx = i2; }
    }

    __shared__ float swv[NWARPS];
    __shared__ int   swi[NWARPS];
    __shared__ bool  is_last;
    if (lane == 0) { swv[warp] = best; swi[warp] = bidx; }
    __syncthreads();

    if (warp == 0) {
        best = (lane < NWARPS) ? swv[lane] : -FLT_MAX;
        bidx = (lane < NWARPS) ? swi[lane] : 0x7FFFFFFF;
        #pragma unroll
        for (int off = NWARPS / 2; off > 0; off >>= 1) {
            float v2 = __shfl_down_sync(0xffffffffu, best, off);
            int   i2 = __shfl_down_sync(0xffffffffu, bidx, off);
            if (v2 > best || (v2 == best && i2 < bidx)) { best = v2; bidx = i2; }
        }

        if (lane == 0) {
            const int idx = bidx;
            const float* __restrict__ pk = pred + (size_t)bk * CVAL * HW;
            const float* __restrict__ g  = gt   + (size_t)bk * CVAL;
            float loss = 0.0f;
            #pragma unroll
            for (int c = 0; c < CVAL; ++c) {
                float d = pk[c * HW + idx] - g[c];
                loss = fmaf(d, d, loss);
            }
            g_labelloss_scratch[bk] = loss;
            __threadfence();                              // scratch before count
            unsigned cnt = atomicAdd(&g_labelloss_count, 1u);
            is_last = (cnt == NBK - 1);
        }
    }
    __syncthreads();

    // ---- Phase 5: last CTA computes the per-batch mean (fixed order) ----
    if (is_last) {
        __threadfence();                                  // acquire all scratch writes
        if (tid < BVAL) {
            float s = 0.0f;
            #pragma unroll
            for (int k = 0; k < KVAL; ++k)
                s += g_labelloss_scratch[tid * KVAL + k];
            out[tid] = s * (1.0f / (float)KVAL);
        }
        if (tid == 0) g_labelloss_count = 0;              // reset for graph replay
    }
}

extern "C" void kernel_launch(void* const* d_in, const int* in_sizes, int n_in,
                              void* d_out, int out_size)
{
    const float* pred    = (const float*)d_in[0];
    const float* gt      = (const float*)d_in[1];
    const float* heatmap = (const float*)d_in[2];
    float* out = (float*)d_out;

    labelloss_fused_kernel<<<NBK, NTHREADS>>>(pred, gt, heatmap, out);
}